// round 6
// baseline (speedup 1.0000x reference)
#include <cuda_runtime.h>
#include <math.h>

// ---------------------------------------------------------------------------
// SoftCluster_adaptiveK — round 6: ONE persistent kernel does everything
// (gumbel weights, xsq, k-means++ init with in-kernel select, all iterations).
//  * group-transpose warp reduction: 3K+2 shfl per row instead of 5K
//  * volatile-poll grid barrier
// ---------------------------------------------------------------------------

#define D      256
#define KMAX   6
#define GRID1  148
#define T1     384
#define NW1    12
#define TOT_W  (GRID1 * NW1)
#define TOLV   1e-5

typedef unsigned long long u64;

// ---- device scratch (static; zero-init at load; no allocation anywhere) ----
__device__ float  g_centers[KMAX * D];
__device__ float  g_prev[KMAX * D];
__device__ float  g_csq[KMAX];
__device__ float  g_w[KMAX];
__device__ float  g_P[GRID1 * KMAX * D];
__device__ float  g_Pc[GRID1 * KMAX];
__device__ double g_shiftp[KMAX];
__device__ float  g_dmin[131072];
__device__ float  g_xsq[131072];
__device__ double g_bsum[GRID1];
__device__ int    g_maxiters;
__device__ int    g_bar_count;
__device__ int    g_bar_phase;

// ---- helpers ----
__device__ __forceinline__ u64 pk2(float lo, float hi) {
    u64 r; asm("mov.b64 %0,{%1,%2};" : "=l"(r) : "f"(lo), "f"(hi)); return r;
}
__device__ __forceinline__ void upk2(u64 v, float& lo, float& hi) {
    asm("mov.b64 {%0,%1},%2;" : "=f"(lo), "=f"(hi) : "l"(v));
}
__device__ __forceinline__ u64 fma2(u64 a, u64 b, u64 c) {
    u64 r; asm("fma.rn.f32x2 %0,%1,%2,%3;" : "=l"(r) : "l"(a), "l"(b), "l"(c)); return r;
}
__device__ __forceinline__ u64 mul2(u64 a, u64 b) {
    u64 r; asm("mul.rn.f32x2 %0,%1,%2;" : "=l"(r) : "l"(a), "l"(b)); return r;
}
__device__ __forceinline__ float wsum(float v) {
    #pragma unroll
    for (int m = 16; m; m >>= 1) v += __shfl_xor_sync(0xffffffffu, v, m);
    return v;
}
__device__ __forceinline__ float wsum8(float v) {
    v += __shfl_xor_sync(0xffffffffu, v, 1);
    v += __shfl_xor_sync(0xffffffffu, v, 2);
    v += __shfl_xor_sync(0xffffffffu, v, 4);
    return v;
}
__device__ __forceinline__ float wmin8(float v) {
    v = fminf(v, __shfl_xor_sync(0xffffffffu, v, 1));
    v = fminf(v, __shfl_xor_sync(0xffffffffu, v, 2));
    v = fminf(v, __shfl_xor_sync(0xffffffffu, v, 4));
    return v;
}
__device__ __forceinline__ float dot4(float4 a, float4 b) {
    return a.x * b.x + a.y * b.y + a.z * b.z + a.w * b.w;
}

// grid barrier: atomic arrival, volatile-load polling (no RMW contention)
__device__ __forceinline__ void grid_sync() {
    __syncthreads();
    if (threadIdx.x == 0) {
        __threadfence();
        volatile int* vp = &g_bar_phase;
        int ph = *vp;
        if (atomicAdd(&g_bar_count, 1) == (int)gridDim.x - 1) {
            atomicExch(&g_bar_count, 0);
            __threadfence();
            *vp = ph + 1;
        } else {
            while (*vp == ph) { }
            __threadfence();
        }
    }
    __syncthreads();
}

// ---------------------------------------------------------------------------
// The one kernel.
// ---------------------------------------------------------------------------
template <int K>
__global__ void __launch_bounds__(T1, 1) k_all(
        const float* __restrict__ x,
        const float* __restrict__ logits,
        const float* __restrict__ gumbel,
        const float* __restrict__ uinit,
        const int*   __restrict__ maxit_p,
        float* __restrict__ out_r,
        float* __restrict__ out_c,
        int N) {
    __shared__ float4 s_acc4[K * 64];
    __shared__ float  s_cnt[K];
    __shared__ double s_red[T1 >= 512 ? T1 : 512];
    __shared__ double s_base;
    __shared__ int    s_pick;

    int tid  = threadIdx.x;
    int lane = tid & 31;
    int warp = tid >> 5;
    int bid  = blockIdx.x;
    int jl   = lane & 7;

    // ================= phase 0: block 0 computes weights + center 0 ========
    if (bid == 0) {
        if (tid == 0) {
            g_maxiters = maxit_p[0];
            float l[KMAX]; float m = -3.4e38f;
            for (int j = 0; j < KMAX; j++) { l[j] = logits[j] + gumbel[j]; m = fmaxf(m, l[j]); }
            float s = 0.f, e[KMAX];
            for (int j = 0; j < KMAX; j++) { e[j] = expf(l[j] - m); s += e[j]; }
            for (int j = 0; j < KMAX; j++) g_w[j] = e[j] / s;
        }
        for (int i = tid; i < KMAX * D; i += T1) g_prev[i] = 0.f;
        float f = uinit[0] * (float)N;
        int idx = (int)f;
        if (idx > N - 1) idx = N - 1;
        if (idx < 0) idx = 0;
        if (tid < D) {
            float v = x[(size_t)idx * D + tid];
            g_centers[tid] = v;
            s_red[tid] = (double)v * (double)v;
        }
        __syncthreads();
        for (int s = 128; s; s >>= 1) {
            if (tid < s) s_red[tid] += s_red[tid + s];
            __syncthreads();
        }
        if (tid == 0) g_csq[0] = (float)s_red[0];
    }
    grid_sync();
    int maxit = __ldcg(&g_maxiters);

    // ================= phase 1: xsq + k-means++ init ========================
    int chunk = (N + GRID1 - 1) / GRID1;
    int st = bid * chunk;
    int en = min(st + chunk, N);

    if (K >= 2) {
        for (int i = 1; i < K; i++) {
            // ---- dmin pass over contiguous own chunk ----
            const float4* cb = (const float4*)(g_centers + (size_t)(i - 1) * D);
            float4 c0 = __ldcg(cb + lane), c1 = __ldcg(cb + lane + 32);
            float  cs = __ldcg(&g_csq[i - 1]);
            double wsumd = 0.0;
            for (int row = st + warp; row < en; row += NW1) {
                const float4* xr = (const float4*)x + (size_t)row * (D / 4);
                float4 a0 = __ldg(xr + lane);
                float4 a1 = __ldg(xr + lane + 32);
                float dp = dot4(a0, c0) + dot4(a1, c1);
                if (i == 1) {
                    float xs = dot4(a0, a0) + dot4(a1, a1);
                    #pragma unroll
                    for (int m = 16; m; m >>= 1) {
                        dp += __shfl_xor_sync(0xffffffffu, dp, m);
                        xs += __shfl_xor_sync(0xffffffffu, xs, m);
                    }
                    if (lane == 0) {
                        g_xsq[row] = xs;
                        float d = sqrtf(fmaxf(xs + cs - 2.f * dp, 1e-12f));
                        g_dmin[row] = d;
                        wsumd += (double)d;
                    }
                } else {
                    dp = wsum(dp);
                    if (lane == 0) {
                        float d = sqrtf(fmaxf(g_xsq[row] + cs - 2.f * dp, 1e-12f));
                        float nd = fminf(g_dmin[row], d);
                        g_dmin[row] = nd;
                        wsumd += (double)nd;
                    }
                }
            }
            if (lane == 0) s_red[warp] = wsumd;
            __syncthreads();
            if (tid == 0) {
                double s = 0.0;
                #pragma unroll
                for (int w = 0; w < NW1; w++) s += s_red[w];
                g_bsum[bid] = s;
            }
            grid_sync();

            // ---- select (block 0 only) ----
            if (bid == 0) {
                // level 1: scan 148 block sums (pad to 256)
                double v = (tid < GRID1) ? __ldcg(&g_bsum[tid]) : 0.0;
                if (tid < 256) s_red[tid] = v;
                __syncthreads();
                for (int off = 1; off < 256; off <<= 1) {
                    double u = (tid >= off && tid < 256) ? s_red[tid - off] : 0.0;
                    __syncthreads();
                    if (tid < 256) s_red[tid] += u;
                    __syncthreads();
                }
                double total  = s_red[255];
                double target = (double)uinit[i] * total;
                if (tid == 0) {
                    s_pick = GRID1 - 1;
                    s_base = total - __ldcg(&g_bsum[GRID1 - 1]);
                }
                __syncthreads();
                if (tid < GRID1) {
                    double incl = s_red[tid], excl = incl - v;
                    if (excl < target && target <= incl) { s_pick = tid; s_base = excl; }
                }
                __syncthreads();
                int    tb    = s_pick;
                double resid = target - s_base;
                int sst = tb * chunk;
                int sen = min(sst + chunk, N);
                __syncthreads();
                // level 2: 2 rows per thread, Hillis-Steele over T1
                int r0 = sst + 2 * tid, r1 = r0 + 1;
                double d0 = (r0 < sen) ? (double)__ldcg(&g_dmin[r0]) : 0.0;
                double d1 = (r1 < sen) ? (double)__ldcg(&g_dmin[r1]) : 0.0;
                double pv = d0 + d1;
                s_red[tid] = pv;
                __syncthreads();
                for (int off = 1; off < T1; off <<= 1) {
                    double u = (tid >= off) ? s_red[tid - off] : 0.0;
                    __syncthreads();
                    s_red[tid] += u;
                    __syncthreads();
                }
                if (tid == 0) s_pick = sen - 1 - sst;
                __syncthreads();
                {
                    double incl = s_red[tid], excl = incl - pv;
                    if (excl < resid && resid <= incl) {
                        double c = excl + d0;
                        int f = (c >= resid && r0 < sen) ? r0 : r1;
                        s_pick = f - sst;
                    }
                }
                __syncthreads();
                int idx = sst + s_pick;
                if (idx > N - 1) idx = N - 1;
                if (tid < D) {
                    float cv = __ldg(&x[(size_t)idx * D + tid]);
                    g_centers[i * D + tid] = cv;
                    s_red[tid] = (double)cv * (double)cv;
                }
                __syncthreads();
                for (int s = 128; s; s >>= 1) {
                    if (tid < s) s_red[tid] += s_red[tid + s];
                    __syncthreads();
                }
                if (tid == 0) g_csq[i] = (float)s_red[0];
            }
            grid_sync();
        }
    } else {
        // K == 1: still need xsq for the iteration loop
        for (int row = st + warp; row < en; row += NW1) {
            const float4* xr = (const float4*)x + (size_t)row * (D / 4);
            float4 a0 = __ldg(xr + lane);
            float4 a1 = __ldg(xr + lane + 32);
            float xs = wsum(dot4(a0, a0) + dot4(a1, a1));
            if (lane == 0) g_xsq[row] = xs;
        }
        grid_sync();
    }

    // ================= maxit < 1: r = zeros, centers = init =================
    if (maxit < 1) {
        size_t tot = (size_t)N * K;
        for (size_t ii = (size_t)bid * T1 + tid; ii < tot; ii += (size_t)GRID1 * T1)
            out_r[ii] = 0.f;
        if (bid == 0)
            for (int ii = tid; ii < K * D; ii += T1) out_c[ii] = __ldcg(&g_centers[ii]);
        return;
    }

    // ================= phase 2: soft k-means iterations ======================
    float w_l = (jl < K) ? __ldg(&g_w[jl]) : 0.f;

    for (int t = 0; t < maxit; t++) {
        float csq_l = (jl < K) ? __ldcg(&g_csq[jl]) : 0.f;
        u64 c_pk[K][4];
        const float4* cb = (const float4*)g_centers;
        #pragma unroll
        for (int j = 0; j < K; j++) {
            float4 c0 = __ldcg(cb + j * 64 + lane);
            float4 c1 = __ldcg(cb + j * 64 + 32 + lane);
            c_pk[j][0] = pk2(c0.x, c0.y); c_pk[j][1] = pk2(c0.z, c0.w);
            c_pk[j][2] = pk2(c1.x, c1.y); c_pk[j][3] = pk2(c1.z, c1.w);
        }
        for (int i = tid; i < K * 64; i += T1) s_acc4[i] = make_float4(0.f, 0.f, 0.f, 0.f);
        if (tid < K) s_cnt[tid] = 0.f;
        __syncthreads();

        u64 acc2[K][4];
        #pragma unroll
        for (int j = 0; j < K; j++) {
            #pragma unroll
            for (int u = 0; u < 4; u++) acc2[j][u] = 0ull;
        }
        float cnt_l = 0.f;

        // ---- main pass: two interleaved rows per step ----
        int row = bid * NW1 + warp;
        while (row + TOT_W < N) {
            int rA = row, rB = row + TOT_W;
            const float4* xA = (const float4*)x + (size_t)rA * (D / 4);
            const float4* xB = (const float4*)x + (size_t)rB * (D / 4);
            float4 a0A = __ldg(xA + lane);
            float4 a0B = __ldg(xB + lane);
            float4 a1A = __ldg(xA + lane + 32);
            float4 a1B = __ldg(xB + lane + 32);
            float  xsA = __ldg(g_xsq + rA);
            float  xsB = __ldg(g_xsq + rB);
            u64 pA0 = pk2(a0A.x, a0A.y), pA1 = pk2(a0A.z, a0A.w);
            u64 pA2 = pk2(a1A.x, a1A.y), pA3 = pk2(a1A.z, a1A.w);
            u64 pB0 = pk2(a0B.x, a0B.y), pB1 = pk2(a0B.z, a0B.w);
            u64 pB2 = pk2(a1B.x, a1B.y), pB3 = pk2(a1B.z, a1B.w);
            float dpA[K], dpB[K];
            #pragma unroll
            for (int j = 0; j < K; j++) {
                u64 tA = mul2(pA0, c_pk[j][0]);
                u64 tB = mul2(pB0, c_pk[j][0]);
                tA = fma2(pA1, c_pk[j][1], tA);
                tB = fma2(pB1, c_pk[j][1], tB);
                tA = fma2(pA2, c_pk[j][2], tA);
                tB = fma2(pB2, c_pk[j][2], tB);
                tA = fma2(pA3, c_pk[j][3], tA);
                tB = fma2(pB3, c_pk[j][3], tB);
                float loA, hiA, loB, hiB;
                upk2(tA, loA, hiA); upk2(tB, loB, hiB);
                dpA[j] = loA + hiA; dpB[j] = loB + hiB;
            }
            // reduce within 8-lane groups (3 rounds x K)
            #pragma unroll
            for (int m = 4; m; m >>= 1) {
                #pragma unroll
                for (int j = 0; j < K; j++) {
                    dpA[j] += __shfl_xor_sync(0xffffffffu, dpA[j], m);
                    dpB[j] += __shfl_xor_sync(0xffffffffu, dpB[j], m);
                }
            }
            // select own cluster (jl), then 2 cross-group rounds
            float myA = dpA[0], myB = dpB[0];
            #pragma unroll
            for (int j = 1; j < K; j++) {
                bool p = (jl == j);
                myA = p ? dpA[j] : myA;
                myB = p ? dpB[j] : myB;
            }
            myA += __shfl_xor_sync(0xffffffffu, myA, 8);
            myB += __shfl_xor_sync(0xffffffffu, myB, 8);
            myA += __shfl_xor_sync(0xffffffffu, myA, 16);
            myB += __shfl_xor_sync(0xffffffffu, myB, 16);

            float dA = sqrtf(fmaxf(xsA + csq_l - 2.f * myA, 1e-12f));
            float dB = sqrtf(fmaxf(xsB + csq_l - 2.f * myB, 1e-12f));
            float mnA = wmin8((jl < K) ? dA : 3.4e38f);
            float mnB = wmin8((jl < K) ? dB : 3.4e38f);
            float eA = w_l * __expf(mnA - dA);
            float eB = w_l * __expf(mnB - dB);
            float sA = wsum8(eA);
            float sB = wsum8(eB);
            float rvA = __fdividef(eA, sA);
            float rvB = __fdividef(eB, sB);
            if (lane < K) {
                out_r[(size_t)rA * K + lane] = rvA;
                out_r[(size_t)rB * K + lane] = rvB;
            }
            cnt_l += rvA + rvB;
            #pragma unroll
            for (int j = 0; j < K; j++) {
                float rbA = __shfl_sync(0xffffffffu, rvA, j);
                float rbB = __shfl_sync(0xffffffffu, rvB, j);
                u64 r2A = pk2(rbA, rbA);
                u64 r2B = pk2(rbB, rbB);
                acc2[j][0] = fma2(r2A, pA0, acc2[j][0]);
                acc2[j][1] = fma2(r2A, pA1, acc2[j][1]);
                acc2[j][2] = fma2(r2A, pA2, acc2[j][2]);
                acc2[j][3] = fma2(r2A, pA3, acc2[j][3]);
                acc2[j][0] = fma2(r2B, pB0, acc2[j][0]);
                acc2[j][1] = fma2(r2B, pB1, acc2[j][1]);
                acc2[j][2] = fma2(r2B, pB2, acc2[j][2]);
                acc2[j][3] = fma2(r2B, pB3, acc2[j][3]);
            }
            row += 2 * TOT_W;
        }
        if (row < N) {  // single-row tail
            const float4* xr = (const float4*)x + (size_t)row * (D / 4);
            float4 a0 = __ldg(xr + lane);
            float4 a1 = __ldg(xr + lane + 32);
            float  xs = __ldg(g_xsq + row);
            u64 p0 = pk2(a0.x, a0.y), p1 = pk2(a0.z, a0.w);
            u64 p2 = pk2(a1.x, a1.y), p3 = pk2(a1.z, a1.w);
            float dp[K];
            #pragma unroll
            for (int j = 0; j < K; j++) {
                u64 tt = mul2(p0, c_pk[j][0]);
                tt = fma2(p1, c_pk[j][1], tt);
                tt = fma2(p2, c_pk[j][2], tt);
                tt = fma2(p3, c_pk[j][3], tt);
                float lo, hi; upk2(tt, lo, hi);
                dp[j] = lo + hi;
            }
            #pragma unroll
            for (int m = 4; m; m >>= 1) {
                #pragma unroll
                for (int j = 0; j < K; j++)
                    dp[j] += __shfl_xor_sync(0xffffffffu, dp[j], m);
            }
            float myv = dp[0];
            #pragma unroll
            for (int j = 1; j < K; j++) myv = (jl == j) ? dp[j] : myv;
            myv += __shfl_xor_sync(0xffffffffu, myv, 8);
            myv += __shfl_xor_sync(0xffffffffu, myv, 16);
            float dval = sqrtf(fmaxf(xs + csq_l - 2.f * myv, 1e-12f));
            float dmn  = wmin8((jl < K) ? dval : 3.4e38f);
            float ev   = w_l * __expf(dmn - dval);
            float ssum = wsum8(ev);
            float rv   = __fdividef(ev, ssum);
            if (lane < K) out_r[(size_t)row * K + lane] = rv;
            cnt_l += rv;
            #pragma unroll
            for (int j = 0; j < K; j++) {
                float rb = __shfl_sync(0xffffffffu, rv, j);
                u64 r2 = pk2(rb, rb);
                acc2[j][0] = fma2(r2, p0, acc2[j][0]);
                acc2[j][1] = fma2(r2, p1, acc2[j][1]);
                acc2[j][2] = fma2(r2, p2, acc2[j][2]);
                acc2[j][3] = fma2(r2, p3, acc2[j][3]);
            }
        }

        // ---- deterministic sequential warp combine ----
        for (int w = 0; w < NW1; w++) {
            if (warp == w) {
                #pragma unroll
                for (int j = 0; j < K; j++) {
                    float lo0, hi0, lo1, hi1;
                    float4 v = s_acc4[j * 64 + lane];
                    upk2(acc2[j][0], lo0, hi0);
                    upk2(acc2[j][1], lo1, hi1);
                    v.x += lo0; v.y += hi0; v.z += lo1; v.w += hi1;
                    s_acc4[j * 64 + lane] = v;
                    v = s_acc4[j * 64 + 32 + lane];
                    upk2(acc2[j][2], lo0, hi0);
                    upk2(acc2[j][3], lo1, hi1);
                    v.x += lo0; v.y += hi0; v.z += lo1; v.w += hi1;
                    s_acc4[j * 64 + 32 + lane] = v;
                }
                if (lane < K) s_cnt[lane] += cnt_l;
            }
            __syncthreads();
        }
        {
            float4* Pb = (float4*)(g_P + (size_t)bid * (KMAX * D));
            for (int i = tid; i < K * 64; i += T1) Pb[i] = s_acc4[i];
            if (tid < K) g_Pc[bid * KMAX + tid] = s_cnt[tid];
        }

        grid_sync();

        // ---- center update: block j < K owns cluster j ----
        if (bid < K) {
            int j = bid;
            double c = (tid < GRID1) ? (double)__ldcg(&g_Pc[tid * KMAX + j]) : 0.0;
            s_red[tid] = c;
            __syncthreads();
            for (int s = 256; s; s >>= 1) {
                if (tid < s && tid + s < T1) s_red[tid] += s_red[tid + s];
                __syncthreads();
            }
            double cnt = s_red[0];
            __syncthreads();

            double v0 = 0.0, v1 = 0.0;
            if (tid < 256) {
                int e = j * D + tid;
                double su[8];
                #pragma unroll
                for (int u = 0; u < 8; u++) su[u] = 0.0;
                int p = 0;
                for (; p + 8 <= GRID1; p += 8) {
                    #pragma unroll
                    for (int u = 0; u < 8; u++)
                        su[u] += (double)__ldcg(&g_P[(size_t)(p + u) * (KMAX * D) + e]);
                }
                for (int u = 0; p < GRID1; p++, u++)
                    su[u] += (double)__ldcg(&g_P[(size_t)p * (KMAX * D) + e]);
                double sum = ((su[0] + su[1]) + (su[2] + su[3]))
                           + ((su[4] + su[5]) + (su[6] + su[7]));
                float ncf = (float)(sum / cnt);
                g_centers[e] = ncf;
                float pvv = g_prev[e];
                g_prev[e] = ncf;
                double df = (double)(ncf - pvv);
                v0 = df * df;
                v1 = (double)ncf * (double)ncf;
            }
            s_red[tid] = v0;
            __syncthreads();
            for (int s = 256; s; s >>= 1) {
                if (tid < s && tid + s < T1) s_red[tid] += s_red[tid + s];
                __syncthreads();
            }
            if (tid == 0) g_shiftp[j] = s_red[0];
            __syncthreads();
            s_red[tid] = v1;
            __syncthreads();
            for (int s = 256; s; s >>= 1) {
                if (tid < s && tid + s < T1) s_red[tid] += s_red[tid + s];
                __syncthreads();
            }
            if (tid == 0) g_csq[j] = (float)s_red[0];
        }

        grid_sync();

        double sh = 0.0;
        #pragma unroll
        for (int j = 0; j < K; j++) sh += __ldcg(&g_shiftp[j]);
        if (sqrt(sh) < TOLV) break;
    }

    if (bid == 0)
        for (int i = tid; i < K * D; i += T1) out_c[i] = __ldcg(&g_centers[i]);
}

// ---------------------------------------------------------------------------
extern "C" void kernel_launch(void* const* d_in, const int* in_sizes, int n_in,
                              void* d_out, int out_size) {
    const float* x      = (const float*)d_in[0];
    const float* logits = (const float*)d_in[1];
    const float* gumbel = (const float*)d_in[2];
    const float* uinit  = (const float*)d_in[3];
    const int*   maxit  = (const int*)d_in[4];

    int N = in_sizes[0] / D;
    int k = out_size / (N + D);
    if (k < 1) k = 1;
    if (k > KMAX) k = KMAX;

    float* out_c = (float*)d_out;
    float* out_r = out_c + (size_t)k * D;

    switch (k) {
        case 1: k_all<1><<<GRID1, T1>>>(x, logits, gumbel, uinit, maxit, out_r, out_c, N); break;
        case 2: k_all<2><<<GRID1, T1>>>(x, logits, gumbel, uinit, maxit, out_r, out_c, N); break;
        case 3: k_all<3><<<GRID1, T1>>>(x, logits, gumbel, uinit, maxit, out_r, out_c, N); break;
        case 4: k_all<4><<<GRID1, T1>>>(x, logits, gumbel, uinit, maxit, out_r, out_c, N); break;
        case 5: k_all<5><<<GRID1, T1>>>(x, logits, gumbel, uinit, maxit, out_r, out_c, N); break;
        default: k_all<6><<<GRID1, T1>>>(x, logits, gumbel, uinit, maxit, out_r, out_c, N); break;
    }
}